// round 16
// baseline (speedup 1.0000x reference)
#include <cuda_runtime.h>
#include <math.h>
#include <stdint.h>

#define TT 2048
#define DD 1024
#define FF 2048
#define CC 4
#define EE 4
#define NEXP 16
#define EPSL 1e-5f

#if defined(__CUDA_ARCH_FEAT_SM103_ALL) || defined(__CUDA_ARCH_FEAT_SM100_ALL) || \
    (defined(__CUDA_ARCH_SPECIFIC__) && (__CUDA_ARCH_SPECIFIC__ >= 1000))
#define TC_OK 1
#else
#define TC_OK 0
#endif

// ---------------- device scratch (packed swizzled tile images) ----------------
__device__ float g_A[16ULL*2048ULL*1024ULL];
__device__ float g_H[16ULL*2048ULL*2048ULL];
__device__ float g_Z[16ULL*2048ULL*1024ULL];
__device__ float g_W1t[16ULL*2048ULL*1024ULL];
__device__ float g_W2t[16ULL*2048ULL*1024ULL];
__device__ float g_W3t[16ULL*1024ULL*2048ULL];
__device__ int   g_cnt[NEXP];
__device__ int   g_tok[NEXP*TT];
__device__ float g_mu[TT];
__device__ float g_rstd[TT];
__device__ int   g_sel[TT*2];
__device__ float g_gate[TT*2];
__device__ int   g_islot[TT*4];
__device__ int   g_ipos[TT*4];
__device__ float g_icoef[TT*4];

// ---------------- helpers ----------------
__device__ __forceinline__ float tf32r(float f) {
    uint32_t r;
    asm("cvt.rna.tf32.f32 %0, %1;" : "=r"(r) : "f"(f));
    return __uint_as_float(r);
}
__device__ __forceinline__ uint32_t smem_u32(const void* p) {
    uint32_t a;
    asm("{ .reg .u64 t; cvta.to.shared.u64 t, %1; cvt.u32.u64 %0, t; }" : "=r"(a) : "l"(p));
    return a;
}
#define SWZ128(off) ((off) ^ (((off) >> 3) & 0x70))

__device__ __forceinline__ void block_meanvar_256(float s, float s2, float* rbuf,
                                                  float& mu, float& rs)
{
    int tid = threadIdx.x, lane = tid & 31, w = tid >> 5;
    __syncthreads();
    #pragma unroll
    for (int o = 16; o; o >>= 1) {
        s  += __shfl_down_sync(0xffffffffu, s,  o);
        s2 += __shfl_down_sync(0xffffffffu, s2, o);
    }
    if (lane == 0) { rbuf[w] = s; rbuf[8 + w] = s2; }
    __syncthreads();
    if (tid == 0) {
        float S = 0.f, S2 = 0.f;
        #pragma unroll
        for (int ww = 0; ww < 8; ww++) { S += rbuf[ww]; S2 += rbuf[8 + ww]; }
        float m = S / (float)DD;
        rbuf[16] = m;
        rbuf[17] = rsqrtf(S2 / (float)DD - m * m + EPSL);
    }
    __syncthreads();
    mu = rbuf[16];
    rs = rbuf[17];
}

// ---------------- small kernels ----------------
__global__ void zero_cnt_kernel()
{
    if (threadIdx.x < NEXP) g_cnt[threadIdx.x] = 0;
}

#define RT_SMEM (20480 * 4)

__global__ void __launch_bounds__(1024, 1)
routing_kernel(const float* __restrict__ x,
               const float* __restrict__ Wrc, const float* __restrict__ brc,
               const float* __restrict__ Wre, const float* __restrict__ bre)
{
    extern __shared__ float sm[];
    float* wrc_s = sm;
    float* wre_s = sm + 4096;

    int tid = threadIdx.x;
    int lane = tid & 31, w = tid >> 5;

    for (int i = tid; i < 4096; i += 1024) {
        int d = i >> 2, c = i & 3;
        wrc_s[c * 1024 + d] = Wrc[i];
    }
    for (int i = tid; i < 16384; i += 1024) {
        int cc = i >> 12, d = (i >> 2) & 1023, e = i & 3;
        wre_s[(cc * 4 + e) * 1024 + d] = Wre[i];
    }
    __syncthreads();

    int t = blockIdx.x * 32 + w;

    float xr[32];
    float s = 0.f, s2 = 0.f;
    #pragma unroll
    for (int r = 0; r < 32; r++) {
        float v = x[(size_t)t * DD + lane + 32 * r];
        xr[r] = v; s += v; s2 += v * v;
    }
    #pragma unroll
    for (int o = 16; o; o >>= 1) {
        s  += __shfl_down_sync(0xffffffffu, s,  o);
        s2 += __shfl_down_sync(0xffffffffu, s2, o);
    }
    float lgs[20];
    #pragma unroll
    for (int v = 0; v < 20; v++) {
        const float* wp = (v < CC) ? (wrc_s + v * 1024) : (wre_s + (v - 4) * 1024);
        float acc = 0.f;
        #pragma unroll
        for (int r = 0; r < 32; r++)
            acc += xr[r] * wp[lane + 32 * r];
        #pragma unroll
        for (int o = 16; o; o >>= 1) acc += __shfl_down_sync(0xffffffffu, acc, o);
        lgs[v] = acc;
    }

    if (lane == 0) {
        float mu = s / (float)DD;
        g_mu[t] = mu;
        g_rstd[t] = rsqrtf(s2 / (float)DD - mu * mu + EPSL);

        float p[CC];
        float mx = -1e30f;
        for (int c = 0; c < CC; c++) { p[c] = lgs[c] + brc[c]; mx = fmaxf(mx, p[c]); }
        float ss = 0.f;
        for (int c = 0; c < CC; c++) { p[c] = expf(p[c] - mx); ss += p[c]; }
        for (int c = 0; c < CC; c++) p[c] /= ss;
        int i0 = 0;
        for (int c = 1; c < CC; c++) if (p[c] > p[i0]) i0 = c;
        int i1 = -1;
        for (int c = 0; c < CC; c++) if (c != i0 && (i1 < 0 || p[c] > p[i1])) i1 = c;
        float swt = p[i0] + p[i1];
        int sel[2] = { i0, i1 };
        float gv[2] = { p[i0] / swt, p[i1] / swt };

        for (int sI = 0; sI < 2; sI++) {
            int cc = sel[sI];
            g_sel[t * 2 + sI]  = cc;
            g_gate[t * 2 + sI] = gv[sI];
            float el[EE];
            for (int e = 0; e < EE; e++) el[e] = lgs[4 + cc * 4 + e] + bre[cc * EE + e];
            int e0 = 0;
            for (int e = 1; e < EE; e++) if (el[e] > el[e0]) e0 = e;
            int e1 = -1;
            for (int e = 0; e < EE; e++) if (e != e0 && (e1 < 0 || el[e] > el[e1])) e1 = e;
            float z = expf(el[e1] - el[e0]);
            float w0 = 1.f / (1.f + z), w1 = z / (1.f + z);
            int   eS[2] = { e0, e1 };
            float wS[2] = { w0, w1 };
            for (int q = 0; q < 2; q++) {
                int slot = cc * EE + eS[q];
                int pos = atomicAdd(&g_cnt[slot], 1);
                g_tok[slot * TT + pos] = t;
                g_islot[t * 4 + sI * 2 + q] = slot;
                g_ipos [t * 4 + sI * 2 + q] = pos;
                g_icoef[t * 4 + sI * 2 + q] = wS[q];
            }
        }
    }
}

// gather + input LN + tf32 round -> packed swizzled images in g_A
__global__ void prep_kernel(const float* __restrict__ x,
                            const float* __restrict__ ling, const float* __restrict__ linb)
{
    int idx = blockIdx.y;
    int i = blockIdx.x;
    if (i >= g_cnt[idx]) return;
    int tok = g_tok[idx * TT + i];
    float mu = g_mu[tok], rs = g_rstd[tok];
    const float4* xr = (const float4*)(x + (size_t)tok * DD);
    const float4* gp = (const float4*)(ling + (size_t)idx * DD);
    const float4* bp = (const float4*)(linb + (size_t)idx * DD);
    int d = threadIdx.x;
    float4 xv = xr[d], gv = gp[d], bv = bp[d];
    float4 o;
    o.x = tf32r((xv.x - mu) * rs * gv.x + bv.x);
    o.y = tf32r((xv.y - mu) * rs * gv.y + bv.y);
    o.z = tf32r((xv.z - mu) * rs * gv.z + bv.z);
    o.w = tf32r((xv.w - mu) * rs * gv.w + bv.w);
    char* dst = (char*)g_A
        + ((size_t)idx * 2097152 + (size_t)(d >> 3) * 65536 + (size_t)(i >> 7) * 4096) * 4
        + SWZ128((uint32_t)((i & 127) * 128 + (d & 7) * 16));
    *(float4*)dst = o;
}

// weight pack: in [z][R][C] -> swizzled transposed images.
__global__ void pack_kernel(const float* __restrict__ in, float* __restrict__ out,
                            int R, int C, int dualmap)
{
    __shared__ float t[32][132];
    int z = blockIdx.z;
    int idx = dualmap ? ((z >> 1) * 4 + ((z & 1) ? 3 : 0)) : z;
    const float* ip = in + (size_t)idx * R * C;
    float* op = out + (size_t)idx * R * C;
    int n0 = blockIdx.x * 128, k0 = blockIdx.y * 32;
    int tid = threadIdx.x;
    int lane = tid & 31, w = tid >> 5;

    #pragma unroll
    for (int r = 0; r < 4; r++) {
        int row = w * 4 + r;
        float4 v = *(const float4*)&ip[(size_t)(k0 + row) * C + n0 + lane * 4];
        float4 o;
        o.x = tf32r(v.x); o.y = tf32r(v.y); o.z = tf32r(v.z); o.w = tf32r(v.w);
        *(float4*)&t[row][lane * 4] = o;
    }
    __syncthreads();

    #pragma unroll
    for (int j = 0; j < 4; j++) {
        int lin = tid + 256 * j;
        int nl = lin >> 3;
        int u  = lin & 7;
        float4 v = make_float4(t[4*u][nl], t[4*u+1][nl], t[4*u+2][nl], t[4*u+3][nl]);
        size_t base = ((size_t)(k0 >> 5) * (size_t)(C / 128) + (size_t)blockIdx.x) * 4096;
        char* dst = (char*)op + base * 4 + SWZ128((uint32_t)(nl * 128 + u * 16));
        *(float4*)dst = v;
    }
}

// ================= tcgen05 machinery =================
#if TC_OK
static constexpr uint64_t SMEM_DESC_BASE_SW128 =
    (uint64_t(2)  << 61) | (uint64_t(1) << 46) | (uint64_t(64) << 32) | (uint64_t(1) << 16);
#define MAKE_SMEM_DESC(base_addr) \
    (SMEM_DESC_BASE_SW128 | ((uint64_t)((base_addr) >> 4) & 0x3FFF))
#define IDESC_TF32_N128 ((1u<<4) | (2u<<7) | (2u<<10) | ((128u/8u)<<17) | ((128u/16u)<<24))

__device__ __forceinline__ void umma_tf32(uint32_t d_tmem, uint64_t a_desc,
                                          uint64_t b_desc, uint32_t idesc, uint32_t en)
{
    asm volatile(
        "{\n\t.reg .pred p;\n\t"
        "setp.ne.u32 p, %5, 0;\n\t"
        "tcgen05.mma.cta_group::1.kind::tf32 [%0], %1, %2, %3, {%4, %4, %4, %4}, p;\n\t"
        "}"
        :: "r"(d_tmem), "l"(a_desc), "l"(b_desc), "r"(idesc), "r"(0u), "r"(en)
        : "memory");
}
__device__ __forceinline__ void bulk_g2s(uint32_t dst, const void* src,
                                         uint32_t bytes, uint32_t mbar)
{
    asm volatile(
        "cp.async.bulk.shared::cluster.global.mbarrier::complete_tx::bytes [%0], [%1], %2, [%3];\n"
        :: "r"(dst), "l"(src), "r"(bytes), "r"(mbar) : "memory");
}
#define TCGEN05_ALLOC(sa, n) \
    asm volatile("tcgen05.alloc.cta_group::1.sync.aligned.shared::cta.b32 [%0], %1;" \
        :: "r"((uint32_t)(sa)), "r"((uint32_t)(n)) : "memory")
#define TCGEN05_DEALLOC(t, n) \
    asm volatile("tcgen05.dealloc.cta_group::1.sync.aligned.b32 %0, %1;" \
        :: "r"(t), "r"((uint32_t)(n)))
#define TCGEN05_RELINQUISH() \
    asm volatile("tcgen05.relinquish_alloc_permit.cta_group::1.sync.aligned;")
#define TCGEN05_COMMIT(mb) \
    asm volatile("tcgen05.commit.cta_group::1.mbarrier::arrive::one.shared::cluster.b64 [%0];" \
        :: "r"((uint32_t)(mb)) : "memory")
#define TCGEN05_FENCE_AFTER() \
    asm volatile("tcgen05.fence::after_thread_sync;" ::: "memory")
#define TCGEN05_WAIT_LD() \
    asm volatile("tcgen05.wait::ld.sync.aligned;" ::: "memory")
#define TCGEN05_LD_X16(r, ta) \
    asm volatile( \
        "tcgen05.ld.sync.aligned.32x32b.x16.b32 " \
        "{%0, %1, %2, %3, %4, %5, %6, %7, " \
        " %8, %9, %10, %11, %12, %13, %14, %15}, [%16];" \
        : "=r"((r)[0]),  "=r"((r)[1]),  "=r"((r)[2]),  "=r"((r)[3]), \
          "=r"((r)[4]),  "=r"((r)[5]),  "=r"((r)[6]),  "=r"((r)[7]), \
          "=r"((r)[8]),  "=r"((r)[9]),  "=r"((r)[10]), "=r"((r)[11]), \
          "=r"((r)[12]), "=r"((r)[13]), "=r"((r)[14]), "=r"((r)[15]) \
        : "r"(ta))
#define MBARRIER_INIT(mb, c) \
    asm volatile("mbarrier.init.shared.b64 [%0], %1;" \
        :: "r"((uint32_t)(mb)), "r"((uint32_t)(c)) : "memory")
#define MBARRIER_EXPECT_TX(mb, bytes) \
    asm volatile("mbarrier.arrive.expect_tx.shared.b64 _, [%0], %1;" \
        :: "r"((uint32_t)(mb)), "r"((uint32_t)(bytes)) : "memory")
#define MBARRIER_INVAL(mb) \
    asm volatile("mbarrier.inval.shared.b64 [%0];" :: "r"((uint32_t)(mb)) : "memory")
#define MBAR_WAIT(mb, parity) do { \
    uint32_t _m = (uint32_t)(mb); \
    uint32_t _p = (uint32_t)(parity); \
    uint32_t _done; \
    asm volatile( \
        "{\n\t.reg .pred p;\n\t" \
        "mbarrier.try_wait.parity.acquire.cta.shared::cta.b64 p, [%1], %2;\n\t" \
        "selp.b32 %0, 1, 0, p;\n\t}" \
        : "=r"(_done) : "r"(_m), "r"(_p) : "memory"); \
    if (!_done) { \
        asm volatile( \
            "{\n\t.reg .pred P1;\n\t" \
            "WAIT_LOOP_%=:\n\t" \
            "mbarrier.try_wait.parity.acquire.cta.shared::cta.b64 P1, [%0], %1, 0x989680;\n\t" \
            "@P1 bra.uni WAIT_DONE_%=;\n\t" \
            "bra.uni WAIT_LOOP_%=;\n\t" \
            "WAIT_DONE_%=:\n\t}" \
            :: "r"(_m), "r"(_p) : "memory"); \
    } \
} while (0)
#endif

#define NSTG 3
#define STGB  65536u   // dual stage: A 32KB + B 32KB
#define STGS  32768u   // small stage: A 16KB + B 16KB
#define SMEM_DUAL (NSTG * STGB + 1024)
#define SMEM_SMALL (NSTG * STGS + 1024)

// GEMM1 dual experts: BM=256, BN=128 (W1+W2). grid (16, 4, 8). 1 CTA/SM.
__global__ void __launch_bounds__(512, 1)
gemm1_dual_kernel()
{
#if TC_OK
    int z = blockIdx.z;
    int idx = (z >> 1) * 4 + ((z & 1) ? 3 : 0);
    int Nt = g_cnt[idx];
    int m0 = blockIdx.y * 256;
    if (m0 >= Nt) return;
    int n0 = blockIdx.x * 128;

    const float* Aimg  = g_A   + (size_t)idx * 2097152;
    const float* B1img = g_W1t + (size_t)idx * 2097152;
    const float* B2img = g_W2t + (size_t)idx * 2097152;

    extern __shared__ __align__(1024) char smem[];
    uint32_t sb = smem_u32(smem);
    uint32_t ctrl = sb + NSTG * STGB;

    int tid = threadIdx.x;
    int w = tid >> 5;

    if (w == 0) TCGEN05_ALLOC(ctrl, 512);
    if (tid == 0) {
        MBARRIER_INIT(ctrl + 8, 1);
        #pragma unroll
        for (int s2 = 0; s2 < NSTG; ++s2) MBARRIER_INIT(ctrl + 16 + 8 * s2, 1);
    }
    __syncthreads();
    uint32_t tmem;
    asm volatile("ld.shared.b32 %0, [%1];" : "=r"(tmem) : "r"(ctrl));

    const int NCH = DD / 32;
    if (tid == 0) {
        auto load_chunk = [&](int st, int ch) {
            uint32_t mb = ctrl + 16 + 8 * st;
            uint32_t base = sb + st * STGB;
            MBARRIER_EXPECT_TX(mb, 65536u);
            bulk_g2s(base, Aimg + (size_t)ch * 65536 + (size_t)(m0 >> 7) * 4096, 32768, mb);
            bulk_g2s(base + 32768, B1img + (size_t)ch * 65536 + (size_t)(n0 >> 7) * 4096, 16384, mb);
            bulk_g2s(base + 49152, B2img + (size_t)ch * 65536 + (size_t)(n0 >> 7) * 4096, 16384, mb);
        };
        load_chunk(0, 0);
        load_chunk(1, 1);
        for (int it = 0; it < NCH; ++it) {
            int st = it % NSTG;
            if (it >= 1) MBAR_WAIT(ctrl + 8, (it - 1) & 1);
            if (it + 2 < NCH) load_chunk((it + 2) % NSTG, it + 2);
            MBAR_WAIT(ctrl + 16 + 8 * st, (it / NSTG) & 1);
            uint32_t base = sb + st * STGB;
            #pragma unroll
            for (int m = 0; m < 2; ++m) {
                uint64_t ad = MAKE_SMEM_DESC(base + m * 16384u);
                #pragma unroll
                for (int half = 0; half < 2; ++half) {
                    uint64_t bd = MAKE_SMEM_DESC(base + 32768u + half * 16384u);
                    #pragma unroll
                    for (int k = 0; k < 4; ++k)
                        umma_tf32(tmem + m * 256 + half * 128, ad + 2 * k, bd + 2 * k,
                                  IDESC_TF32_N128, (uint32_t)(it > 0 || k > 0));
                }
            }
            TCGEN05_COMMIT(ctrl + 8);
        }
        MBAR_WAIT(ctrl + 8, (NCH - 1) & 1);
    }
    __syncthreads();
    TCGEN05_FENCE_AFTER();

    int lane = tid & 31;
    int sub = w & 3, grp = w >> 2;
    float* Hb = g_H + (size_t)idx * 4194304;
    #pragma unroll
    for (int mblk = 0; mblk < 2; ++mblk) {
        int mrow = m0 + mblk * 128 + sub * 32 + lane;
        bool valid = mrow < Nt;
        uint32_t tb = tmem + mblk * 256;
        #pragma unroll
        for (int cc = 0; cc < 2; ++cc) {
            int coff = grp * 32 + cc * 16;
            int fbase = n0 + coff;
            uint32_t d1[16], d2[16];
            TCGEN05_LD_X16(d1, tb + coff);
            TCGEN05_LD_X16(d2, tb + 128 + coff);
            TCGEN05_WAIT_LD();
            if (valid) {
                #pragma unroll
                for (int v = 0; v < 4; ++v) {
                    float hv[4];
                    #pragma unroll
                    for (int j = 0; j < 4; ++j) {
                        float h1 = __uint_as_float(d1[4 * v + j]);
                        float h2 = __uint_as_float(d2[4 * v + j]);
                        float sg = 1.f / (1.f + expf(-h2));
                        hv[j] = tf32r(h2 * sg * h2 * h1);
                    }
                    int f = fbase + 4 * v;
                    char* dst = (char*)Hb
                        + ((size_t)(f >> 5) * 65536 + (size_t)(mrow >> 7) * 4096) * 4
                        + SWZ128((uint32_t)((mrow & 127) * 128 + ((f & 31) >> 2) * 16));
                    *(float4*)dst = make_float4(hv[0], hv[1], hv[2], hv[3]);
                }
            }
        }
    }
    __syncthreads();
    if (tid == 0) {
        MBARRIER_INVAL(ctrl + 8);
        #pragma unroll
        for (int s2 = 0; s2 < NSTG; ++s2) MBARRIER_INVAL(ctrl + 16 + 8 * s2);
    }
    if (w == 0) { TCGEN05_RELINQUISH(); TCGEN05_DEALLOC(tmem, 512); }
#endif
}

// GEMM1 single experts: BM=128, BN=128 (W1 only). grid (16, 8, 8). 2 CTAs/SM.
__global__ void __launch_bounds__(512, 1)
gemm1_single_kernel()
{
#if TC_OK
    int z = blockIdx.z;
    int idx = (z >> 1) * 4 + ((z & 1) ? 2 : 1);
    int act = (idx & 3) % 3;                       // 1=gelu, 2=relu
    int Nt = g_cnt[idx];
    int m0 = blockIdx.y * 128;
    if (m0 >= Nt) return;
    int n0 = blockIdx.x * 128;

    const float* Aimg = g_A   + (size_t)idx * 2097152;
    const float* Bimg = g_W1t + (size_t)idx * 2097152;

    extern __shared__ __align__(1024) char smem[];
    uint32_t sb = smem_u32(smem);
    uint32_t ctrl = sb + NSTG * STGS;

    int tid = threadIdx.x;
    int w = tid >> 5;

    if (w == 0) TCGEN05_ALLOC(ctrl, 256);
    if (tid == 0) {
        MBARRIER_INIT(ctrl + 8, 1);
        #pragma unroll
        for (int s2 = 0; s2 < NSTG; ++s2) MBARRIER_INIT(ctrl + 16 + 8 * s2, 1);
    }
    __syncthreads();
    uint32_t tmem;
    asm volatile("ld.shared.b32 %0, [%1];" : "=r"(tmem) : "r"(ctrl));

    const int NCH = DD / 32;
    if (tid == 0) {
        auto load_chunk = [&](int st, int ch) {
            uint32_t mb = ctrl + 16 + 8 * st;
            uint32_t base = sb + st * STGS;
            MBARRIER_EXPECT_TX(mb, 32768u);
            bulk_g2s(base, Aimg + (size_t)ch * 65536 + (size_t)(m0 >> 7) * 4096, 16384, mb);
            bulk_g2s(base + 16384, Bimg + (size_t)ch * 65536 + (size_t)(n0 >> 7) * 4096, 16384, mb);
        };
        load_chunk(0, 0);
        load_chunk(1, 1);
        for (int it = 0; it < NCH; ++it) {
            int st = it % NSTG;
            if (it >= 1) MBAR_WAIT(ctrl + 8, (it - 1) & 1);
            if (it + 2 < NCH) load_chunk((it + 2) % NSTG, it + 2);
            MBAR_WAIT(ctrl + 16 + 8 * st, (it / NSTG) & 1);
            uint32_t base = sb + st * STGS;
            uint64_t ad = MAKE_SMEM_DESC(base);
            uint64_t bd = MAKE_SMEM_DESC(base + 16384u);
            #pragma unroll
            for (int k = 0; k < 4; ++k)
                umma_tf32(tmem, ad + 2 * k, bd + 2 * k,
                          IDESC_TF32_N128, (uint32_t)(it > 0 || k > 0));
            TCGEN05_COMMIT(ctrl + 8);
        }
        MBAR_WAIT(ctrl + 8, (NCH - 1) & 1);
    }
    __syncthreads();
    TCGEN05_FENCE_AFTER();

    int lane = tid & 31;
    int sub = w & 3, grp = w >> 2;
    int mrow = m0 + sub * 32 + lane;
    bool valid = mrow < Nt;
    float* Hb = g_H + (size_t)idx * 4194304;
    #pragma unroll
    for (int cc = 0; cc < 2; ++cc) {
        int coff = grp * 32 + cc * 16;
        int fbase = n0 + coff;
        uint32_t d1[16];
        TCGEN05_LD_X16(d1, tmem + coff);
        TCGEN05_WAIT_LD();
        if (valid) {
            #pragma unroll
            for (int v = 0; v < 4; ++v) {
                float hv[4];
                #pragma unroll
                for (int j = 0; j < 4; ++j) {
                    float h1 = __uint_as_float(d1[4 * v + j]);
                    float r = (act == 1)
                        ? 0.5f * h1 * (1.f + erff(h1 * 0.70710678118654752f))
                        : fmaxf(h1, 0.f);
                    hv[j] = tf32r(r);
                }
                int f = fbase + 4 * v;
                char* dst = (char*)Hb
                    + ((size_t)(f >> 5) * 65536 + (size_t)(mrow >> 7) * 4096) * 4
                    + SWZ128((uint32_t)((mrow & 127) * 128 + ((f & 31) >> 2) * 16));
                *(float4*)dst = make_float4(hv[0], hv[1], hv[2], hv[3]);
            }
        }
    }
    __syncthreads();
    if (tid == 0) {
        MBARRIER_INVAL(ctrl + 8);
        #pragma unroll
        for (int s2 = 0; s2 < NSTG; ++s2) MBARRIER_INVAL(ctrl + 16 + 8 * s2);
    }
    if (w == 0) { TCGEN05_RELINQUISH(); TCGEN05_DEALLOC(tmem, 256); }
#endif
}

// GEMM2: Z = x + H @ W3^T. BM=128, BN=128. grid (8, 8, 16). 2 CTAs/SM.
__global__ void __launch_bounds__(512, 1)
gemm2_tc_kernel(const float* __restrict__ x)
{
#if TC_OK
    int idx = blockIdx.z;
    int Nt = g_cnt[idx];
    int m0 = blockIdx.y * 128;
    if (m0 >= Nt) return;
    int n0 = blockIdx.x * 128;

    const float* Aimg = g_H   + (size_t)idx * 4194304;
    const float* Bimg = g_W3t + (size_t)idx * 2097152;

    extern __shared__ __align__(1024) char smem[];
    uint32_t sb = smem_u32(smem);
    uint32_t ctrl = sb + NSTG * STGS;

    int tid = threadIdx.x;
    int w = tid >> 5;

    if (w == 0) TCGEN05_ALLOC(ctrl, 256);
    if (tid == 0) {
        MBARRIER_INIT(ctrl + 8, 1);
        #pragma unroll
        for (int s2 = 0; s2 < NSTG; ++s2) MBARRIER_INIT(ctrl + 16 + 8 * s2, 1);
    }
    __syncthreads();
    uint32_t tmem;
    asm volatile("ld.shared.b32 %0, [%1];" : "=r"(tmem) : "r"(ctrl));

    const int NCH = FF / 32;
    if (tid == 0) {
        auto load_chunk = [&](int st, int ch) {
            uint32_t mb = ctrl + 16 + 8 * st;
            uint32_t base = sb + st * STGS;
            MBARRIER_EXPECT_TX(mb, 32768u);
            bulk_g2s(base, Aimg + (size_t)ch * 65536 + (size_t)(m0 >> 7) * 4096, 16384, mb);
            bulk_g2s(base + 16384, Bimg + (size_t)ch * 32768 + (size_t)(n0 >> 7) * 4096, 16384, mb);
        };
        load_chunk(0, 0);
        load_chunk(1, 1);
        for (int it = 0; it < NCH; ++it) {
            int st = it % NSTG;
            if (it >= 1) MBAR_WAIT(ctrl + 8, (it - 1) & 1);
            if (it + 2 < NCH) load_chunk((it + 2) % NSTG, it + 2);
            MBAR_WAIT(ctrl + 16 + 8 * st, (it / NSTG) & 1);
            uint32_t base = sb + st * STGS;
            uint64_t ad = MAKE_SMEM_DESC(base);
            uint64_t bd = MAKE_SMEM_DESC(base + 16384u);
            #pragma unroll
            for (int k = 0; k < 4; ++k)
                umma_tf32(tmem, ad + 2 * k, bd + 2 * k,
                          IDESC_TF32_N128, (uint32_t)(it > 0 || k > 0));
            TCGEN05_COMMIT(ctrl + 8);
        }
        MBAR_WAIT(ctrl + 8, (NCH - 1) & 1);
    }
    __syncthreads();
    TCGEN05_FENCE_AFTER();

    int lane = tid & 31;
    int sub = w & 3, grp = w >> 2;
    int mrow = m0 + sub * 32 + lane;
    bool valid = mrow < Nt;
    int tok = valid ? g_tok[idx * TT + mrow] : 0;
    float* Zb = g_Z + (size_t)idx * TT * DD;
    #pragma unroll
    for (int cc = 0; cc < 2; ++cc) {
        int coff = grp * 32 + cc * 16;
        uint32_t d1[16];
        TCGEN05_LD_X16(d1, tmem + coff);
        TCGEN05_WAIT_LD();
        if (valid) {
            const float4* xr = (const float4*)(x + (size_t)tok * DD + n0 + coff);
            float4* p = (float4*)(Zb + (size_t)mrow * DD + n0 + coff);
            #pragma unroll
            for (int v = 0; v < 4; ++v) {
                float4 xv = xr[v];
                p[v] = make_float4(__uint_as_float(d1[4*v])   + xv.x,
                                   __uint_as_float(d1[4*v+1]) + xv.y,
                                   __uint_as_float(d1[4*v+2]) + xv.z,
                                   __uint_as_float(d1[4*v+3]) + xv.w);
            }
        }
    }
    __syncthreads();
    if (tid == 0) {
        MBARRIER_INVAL(ctrl + 8);
        #pragma unroll
        for (int s2 = 0; s2 < NSTG; ++s2) MBARRIER_INVAL(ctrl + 16 + 8 * s2);
    }
    if (w == 0) { TCGEN05_RELINQUISH(); TCGEN05_DEALLOC(tmem, 256); }
#endif
}

// fused: expert LN + expert combine + cluster LN + gate sum
__global__ void final_kernel(const float* __restrict__ loutg, const float* __restrict__ loutb,
                             const float* __restrict__ clng, const float* __restrict__ clnb,
                             float* __restrict__ out)
{
    int t = blockIdx.x;
    int tid = threadIdx.x;                    // 256
    __shared__ float rbuf[18];
    float o[4] = {};
    #pragma unroll
    for (int sI = 0; sI < 2; sI++) {
        float vcmb[4] = {};
        #pragma unroll
        for (int q = 0; q < 2; q++) {
            int slot = g_islot[t * 4 + sI * 2 + q];
            int pos  = g_ipos [t * 4 + sI * 2 + q];
            float cf = g_icoef[t * 4 + sI * 2 + q];
            const float* y = g_Z + ((size_t)slot * TT + pos) * DD;
            const float* gp = loutg + (size_t)slot * DD;
            const float* bp = loutb + (size_t)slot * DD;
            float v[4], s = 0.f, s2 = 0.f;
            #pragma unroll
            for (int r = 0; r < 4; r++) {
                int d = tid + 256 * r;
                v[r] = y[d]; s += v[r]; s2 += v[r] * v[r];
            }
            float mu, rs;
            block_meanvar_256(s, s2, rbuf, mu, rs);
            #pragma unroll
            for (int r = 0; r < 4; r++) {
                int d = tid + 256 * r;
                vcmb[r] += cf * ((v[r] - mu) * rs * gp[d] + bp[d]);
            }
        }
        float s = 0.f, s2 = 0.f;
        #pragma unroll
        for (int r = 0; r < 4; r++) { s += vcmb[r]; s2 += vcmb[r] * vcmb[r]; }
        float mu, rs;
        block_meanvar_256(s, s2, rbuf, mu, rs);
        int cc = g_sel[t * 2 + sI];
        float gt = g_gate[t * 2 + sI];
        #pragma unroll
        for (int r = 0; r < 4; r++) {
            int d = tid + 256 * r;
            o[r] += gt * ((vcmb[r] - mu) * rs * clng[cc * DD + d] + clnb[cc * DD + d]);
        }
    }
    #pragma unroll
    for (int r = 0; r < 4; r++)
        out[(size_t)t * DD + tid + 256 * r] = o[r];
}

// ---------------- launcher ----------------
extern "C" void kernel_launch(void* const* d_in, const int* in_sizes, int n_in,
                              void* d_out, int out_size)
{
    const float* x     = (const float*)d_in[0];
    const float* W1    = (const float*)d_in[1];
    const float* W2    = (const float*)d_in[2];
    const float* W3    = (const float*)d_in[3];
    const float* ling  = (const float*)d_in[4];
    const float* linb  = (const float*)d_in[5];
    const float* loutg = (const float*)d_in[6];
    const float* loutb = (const float*)d_in[7];
    const float* clng  = (const float*)d_in[8];
    const float* clnb  = (const float*)d_in[9];
    const float* Wrc   = (const float*)d_in[10];
    const float* brc   = (const float*)d_in[11];
    const float* Wre   = (const float*)d_in[12];
    const float* bre   = (const float*)d_in[13];
    float* out = (float*)d_out;

    float* w1t; cudaGetSymbolAddress((void**)&w1t, g_W1t);
    float* w2t; cudaGetSymbolAddress((void**)&w2t, g_W2t);
    float* w3t; cudaGetSymbolAddress((void**)&w3t, g_W3t);

    cudaFuncSetAttribute(gemm1_dual_kernel,
                         cudaFuncAttributeMaxDynamicSharedMemorySize, SMEM_DUAL);
    cudaFuncSetAttribute(gemm1_single_kernel,
                         cudaFuncAttributeMaxDynamicSharedMemorySize, SMEM_SMALL);
    cudaFuncSetAttribute(gemm2_tc_kernel,
                         cudaFuncAttributeMaxDynamicSharedMemorySize, SMEM_SMALL);
    cudaFuncSetAttribute(routing_kernel,
                         cudaFuncAttributeMaxDynamicSharedMemorySize, RT_SMEM);

    // fork-join: packs on side stream, concurrent with routing/prep
    cudaStream_t sB;
    cudaStreamCreateWithFlags(&sB, cudaStreamNonBlocking);
    cudaEvent_t eFork, eJoin12, eJoin3;
    cudaEventCreateWithFlags(&eFork,   cudaEventDisableTiming);
    cudaEventCreateWithFlags(&eJoin12, cudaEventDisableTiming);
    cudaEventCreateWithFlags(&eJoin3,  cudaEventDisableTiming);

    zero_cnt_kernel<<<1, 32>>>();
    cudaEventRecord(eFork, 0);
    cudaStreamWaitEvent(sB, eFork, 0);

    pack_kernel<<<dim3(FF/128, DD/32, 16), 256, 0, sB>>>(W1, w1t, DD, FF, 0);
    pack_kernel<<<dim3(FF/128, DD/32, 8),  256, 0, sB>>>(W2, w2t, DD, FF, 1);
    cudaEventRecord(eJoin12, sB);
    pack_kernel<<<dim3(DD/128, FF/32, 16), 256, 0, sB>>>(W3, w3t, FF, DD, 0);
    cudaEventRecord(eJoin3, sB);

    routing_kernel<<<TT/32, 1024, RT_SMEM>>>(x, Wrc, brc, Wre, bre);
    dim3 gp(TT, NEXP);
    prep_kernel<<<gp, 256>>>(x, ling, linb);

    cudaStreamWaitEvent(0, eJoin12, 0);
    gemm1_dual_kernel<<<dim3(16, 4, 8), 512, SMEM_DUAL>>>();
    gemm1_single_kernel<<<dim3(16, 8, 8), 512, SMEM_SMALL>>>();

    cudaStreamWaitEvent(0, eJoin3, 0);
    gemm2_tc_kernel<<<dim3(8, 8, NEXP), 512, SMEM_SMALL>>>(x);

    final_kernel<<<TT, 256>>>(loutg, loutb, clng, clnb, out);
}

// round 17
// speedup vs baseline: 1.3698x; 1.3698x over previous
#include <cuda_runtime.h>
#include <cuda_bf16.h>
#include <math.h>
#include <stdint.h>

#define TT 2048
#define DD 1024
#define FF 2048
#define CC 4
#define EE 4
#define NEXP 16
#define EPSL 1e-5f

#if defined(__CUDA_ARCH_FEAT_SM103_ALL) || defined(__CUDA_ARCH_FEAT_SM100_ALL) || \
    (defined(__CUDA_ARCH_SPECIFIC__) && (__CUDA_ARCH_SPECIFIC__ >= 1000))
#define TC_OK 1
#else
#define TC_OK 0
#endif

// ---------------- device scratch (packed swizzled bf16 tile images) ----------------
// image block = 128 rows x 128B (64 bf16 = one K-chunk of 64) = 16KB
// g_A  : [idx][ch(16)][mb(16)][16KB]   (4MB/expert)
// g_H  : [idx][ch(32)][mb(16)][16KB]   (8MB/expert)
// g_W1t: [idx][ch(16)][nb(16)][16KB]
// g_W2t: [idx][ch(16)][nb(16)][16KB]
// g_W3t: [idx][ch(32)][nb(8) ][16KB]
__device__ __nv_bfloat16 g_A[16ULL*2048ULL*1024ULL];
__device__ __nv_bfloat16 g_H[16ULL*2048ULL*2048ULL];
__device__ float         g_Z[16ULL*2048ULL*1024ULL];
__device__ __nv_bfloat16 g_W1t[16ULL*2048ULL*1024ULL];
__device__ __nv_bfloat16 g_W2t[16ULL*2048ULL*1024ULL];
__device__ __nv_bfloat16 g_W3t[16ULL*1024ULL*2048ULL];
__device__ int   g_cnt[NEXP];
__device__ int   g_tok[NEXP*TT];
__device__ float g_mu[TT];
__device__ float g_rstd[TT];
__device__ int   g_sel[TT*2];
__device__ float g_gate[TT*2];
__device__ int   g_islot[TT*4];
__device__ int   g_ipos[TT*4];
__device__ float g_icoef[TT*4];

// byte strides
#define A_EXP  4194304ULL
#define A_CH   262144ULL
#define H_EXP  8388608ULL
#define H_CH   262144ULL
#define W1_CH  262144ULL
#define W3_CH  131072ULL

// ---------------- helpers ----------------
__device__ __forceinline__ uint32_t smem_u32(const void* p) {
    uint32_t a;
    asm("{ .reg .u64 t; cvta.to.shared.u64 t, %1; cvt.u32.u64 %0, t; }" : "=r"(a) : "l"(p));
    return a;
}
#define SWZ128(off) ((off) ^ (((off) >> 3) & 0x70))

__device__ __forceinline__ void block_meanvar_256(float s, float s2, float* rbuf,
                                                  float& mu, float& rs)
{
    int tid = threadIdx.x, lane = tid & 31, w = tid >> 5;
    __syncthreads();
    #pragma unroll
    for (int o = 16; o; o >>= 1) {
        s  += __shfl_down_sync(0xffffffffu, s,  o);
        s2 += __shfl_down_sync(0xffffffffu, s2, o);
    }
    if (lane == 0) { rbuf[w] = s; rbuf[8 + w] = s2; }
    __syncthreads();
    if (tid == 0) {
        float S = 0.f, S2 = 0.f;
        #pragma unroll
        for (int ww = 0; ww < 8; ww++) { S += rbuf[ww]; S2 += rbuf[8 + ww]; }
        float m = S / (float)DD;
        rbuf[16] = m;
        rbuf[17] = rsqrtf(S2 / (float)DD - m * m + EPSL);
    }
    __syncthreads();
    mu = rbuf[16];
    rs = rbuf[17];
}

// ---------------- small kernels ----------------
__global__ void zero_cnt_kernel()
{
    if (threadIdx.x < NEXP) g_cnt[threadIdx.x] = 0;
}

#define RT_SMEM (20480 * 4)

__global__ void __launch_bounds__(1024, 1)
routing_kernel(const float* __restrict__ x,
               const float* __restrict__ Wrc, const float* __restrict__ brc,
               const float* __restrict__ Wre, const float* __restrict__ bre)
{
    extern __shared__ float sm[];
    float* wrc_s = sm;
    float* wre_s = sm + 4096;

    int tid = threadIdx.x;
    int lane = tid & 31, w = tid >> 5;

    for (int i = tid; i < 4096; i += 1024) {
        int d = i >> 2, c = i & 3;
        wrc_s[c * 1024 + d] = Wrc[i];
    }
    for (int i = tid; i < 16384; i += 1024) {
        int cc = i >> 12, d = (i >> 2) & 1023, e = i & 3;
        wre_s[(cc * 4 + e) * 1024 + d] = Wre[i];
    }
    __syncthreads();

    int t = blockIdx.x * 32 + w;

    float xr[32];
    float s = 0.f, s2 = 0.f;
    #pragma unroll
    for (int r = 0; r < 32; r++) {
        float v = x[(size_t)t * DD + lane + 32 * r];
        xr[r] = v; s += v; s2 += v * v;
    }
    #pragma unroll
    for (int o = 16; o; o >>= 1) {
        s  += __shfl_down_sync(0xffffffffu, s,  o);
        s2 += __shfl_down_sync(0xffffffffu, s2, o);
    }
    float lgs[20];
    #pragma unroll
    for (int v = 0; v < 20; v++) {
        const float* wp = (v < CC) ? (wrc_s + v * 1024) : (wre_s + (v - 4) * 1024);
        float acc = 0.f;
        #pragma unroll
        for (int r = 0; r < 32; r++)
            acc += xr[r] * wp[lane + 32 * r];
        #pragma unroll
        for (int o = 16; o; o >>= 1) acc += __shfl_down_sync(0xffffffffu, acc, o);
        lgs[v] = acc;
    }

    if (lane == 0) {
        float mu = s / (float)DD;
        g_mu[t] = mu;
        g_rstd[t] = rsqrtf(s2 / (float)DD - mu * mu + EPSL);

        float p[CC];
        float mx = -1e30f;
        for (int c = 0; c < CC; c++) { p[c] = lgs[c] + brc[c]; mx = fmaxf(mx, p[c]); }
        float ss = 0.f;
        for (int c = 0; c < CC; c++) { p[c] = expf(p[c] - mx); ss += p[c]; }
        for (int c = 0; c < CC; c++) p[c] /= ss;
        int i0 = 0;
        for (int c = 1; c < CC; c++) if (p[c] > p[i0]) i0 = c;
        int i1 = -1;
        for (int c = 0; c < CC; c++) if (c != i0 && (i1 < 0 || p[c] > p[i1])) i1 = c;
        float swt = p[i0] + p[i1];
        int sel[2] = { i0, i1 };
        float gv[2] = { p[i0] / swt, p[i1] / swt };

        for (int sI = 0; sI < 2; sI++) {
            int cc = sel[sI];
            g_sel[t * 2 + sI]  = cc;
            g_gate[t * 2 + sI] = gv[sI];
            float el[EE];
            for (int e = 0; e < EE; e++) el[e] = lgs[4 + cc * 4 + e] + bre[cc * EE + e];
            int e0 = 0;
            for (int e = 1; e < EE; e++) if (el[e] > el[e0]) e0 = e;
            int e1 = -1;
            for (int e = 0; e < EE; e++) if (e != e0 && (e1 < 0 || el[e] > el[e1])) e1 = e;
            float z = expf(el[e1] - el[e0]);
            float w0 = 1.f / (1.f + z), w1 = z / (1.f + z);
            int   eS[2] = { e0, e1 };
            float wS[2] = { w0, w1 };
            for (int q = 0; q < 2; q++) {
                int slot = cc * EE + eS[q];
                int pos = atomicAdd(&g_cnt[slot], 1);
                g_tok[slot * TT + pos] = t;
                g_islot[t * 4 + sI * 2 + q] = slot;
                g_ipos [t * 4 + sI * 2 + q] = pos;
                g_icoef[t * 4 + sI * 2 + q] = wS[q];
            }
        }
    }
}

// gather + input LN + bf16 -> packed swizzled images in g_A.  128 threads.
__global__ void prep_kernel(const float* __restrict__ x,
                            const float* __restrict__ ling, const float* __restrict__ linb)
{
    int idx = blockIdx.y;
    int i = blockIdx.x;
    if (i >= g_cnt[idx]) return;
    int tok = g_tok[idx * TT + i];
    float mu = g_mu[tok], rs = g_rstd[tok];
    int u = threadIdx.x;           // unit 0..127 (dims 8u..8u+7)
    const float4* xr = (const float4*)(x + (size_t)tok * DD);
    const float4* gp = (const float4*)(ling + (size_t)idx * DD);
    const float4* bp = (const float4*)(linb + (size_t)idx * DD);
    __nv_bfloat16 o[8];
    #pragma unroll
    for (int h = 0; h < 2; h++) {
        float4 xv = xr[2 * u + h], gv = gp[2 * u + h], bv = bp[2 * u + h];
        o[4*h+0] = __float2bfloat16((xv.x - mu) * rs * gv.x + bv.x);
        o[4*h+1] = __float2bfloat16((xv.y - mu) * rs * gv.y + bv.y);
        o[4*h+2] = __float2bfloat16((xv.z - mu) * rs * gv.z + bv.z);
        o[4*h+3] = __float2bfloat16((xv.w - mu) * rs * gv.w + bv.w);
    }
    char* dst = (char*)g_A + (size_t)idx * A_EXP + (size_t)(u >> 3) * A_CH
        + (size_t)(i >> 7) * 16384 + SWZ128((uint32_t)((i & 127) * 128 + (u & 7) * 16));
    *(float4*)dst = *(float4*)o;
}

// weight pack: fp32 [z][R][C] (k-major) -> bf16 transposed swizzled images.
// tile 64k x 128n per block, 256 threads.
__global__ void pack_kernel(const float* __restrict__ in, __nv_bfloat16* __restrict__ out,
                            int R, int C, int dualmap)
{
    __shared__ __nv_bfloat16 t[64][136];
    int z = blockIdx.z;
    int idx = dualmap ? ((z >> 1) * 4 + ((z & 1) ? 3 : 0)) : z;
    const float* ip = in + (size_t)idx * R * C;
    char* op = (char*)(out + (size_t)idx * R * C);
    int n0 = blockIdx.x * 128, k0 = blockIdx.y * 64;
    int tid = threadIdx.x;

    #pragma unroll
    for (int j = 0; j < 8; j++) {
        int lin = tid + 256 * j;          // 0..2047
        int r  = lin >> 5;                // k row 0..63
        int cu = lin & 31;                // col unit (4 floats)
        float4 v = *(const float4*)&ip[(size_t)(k0 + r) * C + n0 + cu * 4];
        t[r][cu*4+0] = __float2bfloat16(v.x);
        t[r][cu*4+1] = __float2bfloat16(v.y);
        t[r][cu*4+2] = __float2bfloat16(v.z);
        t[r][cu*4+3] = __float2bfloat16(v.w);
    }
    __syncthreads();

    size_t base = ((size_t)(k0 >> 6) * (size_t)(C / 128) + (size_t)blockIdx.x) * 16384;
    #pragma unroll
    for (int j = 0; j < 4; j++) {
        int lin = tid + 256 * j;          // 0..1023
        int nl = lin >> 3;                // n local 0..127
        int u  = lin & 7;                 // 16B unit -> k 8u..8u+7
        __nv_bfloat16 o[8];
        #pragma unroll
        for (int jj = 0; jj < 8; jj++) o[jj] = t[u * 8 + jj][nl];
        char* dst = op + base + SWZ128((uint32_t)(nl * 128 + u * 16));
        *(float4*)dst = *(float4*)o;
    }
}

// ================= tcgen05 machinery =================
#if TC_OK
static constexpr uint64_t SMEM_DESC_BASE_SW128 =
    (uint64_t(2)  << 61) | (uint64_t(1) << 46) | (uint64_t(64) << 32) | (uint64_t(1) << 16);
#define MAKE_SMEM_DESC(base_addr) \
    (SMEM_DESC_BASE_SW128 | ((uint64_t)((base_addr) >> 4) & 0x3FFF))
// kind::f16, bf16 x bf16 -> f32, M=128, N=128
#define IDESC_BF16_N128 ((1u<<4) | (1u<<7) | (1u<<10) | ((128u/8u)<<17) | ((128u/16u)<<24))

__device__ __forceinline__ void umma_bf16(uint32_t d_tmem, uint64_t a_desc,
                                          uint64_t b_desc, uint32_t idesc, uint32_t en)
{
    asm volatile(
        "{\n\t.reg .pred p;\n\t"
        "setp.ne.u32 p, %5, 0;\n\t"
        "tcgen05.mma.cta_group::1.kind::f16 [%0], %1, %2, %3, {%4, %4, %4, %4}, p;\n\t"
        "}"
        :: "r"(d_tmem), "l"(a_desc), "l"(b_desc), "r"(idesc), "r"(0u), "r"(en)
        : "memory");
}
__device__ __forceinline__ void bulk_g2s(uint32_t dst, const void* src,
                                         uint32_t bytes, uint32_t mbar)
{
    asm volatile(
        "cp.async.bulk.shared::cluster.global.mbarrier::complete_tx::bytes [%0], [%1], %2, [%3];\n"
        :: "r"(dst), "l"(src), "r"(bytes), "r"(mbar) : "memory");
}
#define TCGEN05_ALLOC(sa, n) \
    asm volatile("tcgen05.alloc.cta_group::1.sync.aligned.shared::cta.b32 [%0], %1;" \
        :: "r"((uint32_t)(sa)), "r"((uint32_t)(n)) : "memory")
#define TCGEN05_DEALLOC(t, n) \
    asm volatile("tcgen05.dealloc.cta_group::1.sync.aligned.b32 %0, %1;" \
        :: "r"(t), "r"((uint32_t)(n)))
#define TCGEN05_RELINQUISH() \
    asm volatile("tcgen05.relinquish_alloc_permit.cta_group::1.sync.aligned;")
#define TCGEN05_COMMIT(mb) \
    asm volatile("tcgen05.commit.cta_group::1.mbarrier::arrive::one.shared::cluster.b64 [%0];" \
        :: "r"((uint32_t)(mb)) : "memory")
#define TCGEN05_FENCE_AFTER() \
    asm volatile("tcgen05.fence::after_thread_sync;" ::: "memory")
#define TCGEN05_WAIT_LD() \
    asm volatile("tcgen05.wait::ld.sync.aligned;" ::: "memory")
#define TCGEN05_LD_X16(r, ta) \
    asm volatile( \
        "tcgen05.ld.sync.aligned.32x32b.x16.b32 " \
        "{%0, %1, %2, %3, %4, %5, %6, %7, " \
        " %8, %9, %10, %11, %12, %13, %14, %15}, [%16];" \
        : "=r"((r)[0]),  "=r"((r)[1]),  "=r"((r)[2]),  "=r"((r)[3]), \
          "=r"((r)[4]),  "=r"((r)[5]),  "=r"((r)[6]),  "=r"((r)[7]), \
          "=r"((r)[8]),  "=r"((r)[9]),  "=r"((r)[10]), "=r"((r)[11]), \
          "=r"((r)[12]), "=r"((r)[13]), "=r"((r)[14]), "=r"((r)[15]) \
        : "r"(ta))
#define MBARRIER_INIT(mb, c) \
    asm volatile("mbarrier.init.shared.b64 [%0], %1;" \
        :: "r"((uint32_t)(mb)), "r"((uint32_t)(c)) : "memory")
#define MBARRIER_EXPECT_TX(mb, bytes) \
    asm volatile("mbarrier.arrive.expect_tx.shared.b64 _, [%0], %1;" \
        :: "r"((uint32_t)(mb)), "r"((uint32_t)(bytes)) : "memory")
#define MBARRIER_INVAL(mb) \
    asm volatile("mbarrier.inval.shared.b64 [%0];" :: "r"((uint32_t)(mb)) : "memory")
#define MBAR_WAIT(mb, parity) do { \
    uint32_t _m = (uint32_t)(mb); \
    uint32_t _p = (uint32_t)(parity); \
    uint32_t _done; \
    asm volatile( \
        "{\n\t.reg .pred p;\n\t" \
        "mbarrier.try_wait.parity.acquire.cta.shared::cta.b64 p, [%1], %2;\n\t" \
        "selp.b32 %0, 1, 0, p;\n\t}" \
        : "=r"(_done) : "r"(_m), "r"(_p) : "memory"); \
    if (!_done) { \
        asm volatile( \
            "{\n\t.reg .pred P1;\n\t" \
            "WAIT_LOOP_%=:\n\t" \
            "mbarrier.try_wait.parity.acquire.cta.shared::cta.b64 P1, [%0], %1, 0x989680;\n\t" \
            "@P1 bra.uni WAIT_DONE_%=;\n\t" \
            "bra.uni WAIT_LOOP_%=;\n\t" \
            "WAIT_DONE_%=:\n\t}" \
            :: "r"(_m), "r"(_p) : "memory"); \
    } \
} while (0)
#endif

#define NSTG 3
#define STGB 65536u
#define SMEM_TC (NSTG * STGB + 1024)

// GEMM1 (merged): H = act(A @ W^T). bf16 operands, fp32 accum.
// dual:   BM=256, BN=128 (W1+W2), grid.x 0..15
// single: BM=256, BN=256 (W1 only), grid.x 0..7
// NCH = DD/64 = 16 chunks of K=64.
__global__ void __launch_bounds__(512, 1)
gemm1_tc_kernel()
{
#if TC_OK
    int idx = blockIdx.z;
    bool dual = ((idx & 3) % 3) == 0;
    int act = (idx & 3) % 3;
    if (!dual && blockIdx.x >= 8) return;
    int Nt = g_cnt[idx];
    int m0 = blockIdx.y * 256;
    if (m0 >= Nt) return;
    int n0 = blockIdx.x * (dual ? 128 : 256);

    const char* Aimg  = (const char*)g_A   + (size_t)idx * A_EXP;
    const char* B1img = (const char*)g_W1t + (size_t)idx * A_EXP;
    const char* B2img = (const char*)g_W2t + (size_t)idx * A_EXP;

    extern __shared__ __align__(1024) char smem[];
    uint32_t sb = smem_u32(smem);
    uint32_t ctrl = sb + NSTG * STGB;

    int tid = threadIdx.x;
    int w = tid >> 5;

    if (w == 0) TCGEN05_ALLOC(ctrl, 512);
    if (tid == 0) {
        MBARRIER_INIT(ctrl + 8, 1);
        #pragma unroll
        for (int s2 = 0; s2 < NSTG; ++s2) MBARRIER_INIT(ctrl + 16 + 8 * s2, 1);
    }
    __syncthreads();
    uint32_t tmem;
    asm volatile("ld.shared.b32 %0, [%1];" : "=r"(tmem) : "r"(ctrl));

    const int NCH = DD / 64;   // 16
    if (tid == 0) {
        auto load_chunk = [&](int st, int ch) {
            uint32_t mb = ctrl + 16 + 8 * st;
            uint32_t base = sb + st * STGB;
            MBARRIER_EXPECT_TX(mb, 65536u);
            bulk_g2s(base, Aimg + (size_t)ch * A_CH + (size_t)(m0 >> 7) * 16384, 32768, mb);
            if (dual) {
                bulk_g2s(base + 32768, B1img + (size_t)ch * W1_CH + (size_t)(n0 >> 7) * 16384, 16384, mb);
                bulk_g2s(base + 49152, B2img + (size_t)ch * W1_CH + (size_t)(n0 >> 7) * 16384, 16384, mb);
            } else {
                bulk_g2s(base + 32768, B1img + (size_t)ch * W1_CH + (size_t)(n0 >> 7) * 16384, 32768, mb);
            }
        };
        load_chunk(0, 0);
        load_chunk(1, 1);
        for (int it = 0; it < NCH; ++it) {
            int st = it % NSTG;
            if (it >= 1) MBAR_WAIT(ctrl + 8, (it - 1) & 1);
            if (it + 2 < NCH) load_chunk((it + 2) % NSTG, it + 2);
            MBAR_WAIT(ctrl + 16 + 8 * st, (it / NSTG) & 1);
            uint32_t base = sb + st * STGB;
            #pragma unroll
            for (int m = 0; m < 2; ++m) {
                uint64_t ad = MAKE_SMEM_DESC(base + m * 16384u);
                #pragma unroll
                for (int half = 0; half < 2; ++half) {
                    uint64_t bd = MAKE_SMEM_DESC(base + 32768u + half * 16384u);
                    #pragma unroll
                    for (int k = 0; k < 4; ++k)   // K=16 per mma, 4 per chunk
                        umma_bf16(tmem + m * 256 + half * 128, ad + 2 * k, bd + 2 * k,
                                  IDESC_BF16_N128, (uint32_t)(it > 0 || k > 0));
                }
            }
            TCGEN05_COMMIT(ctrl + 8);
        }
        MBAR_WAIT(ctrl + 8, (NCH - 1) & 1);
    }
    __syncthreads();
    TCGEN05_FENCE_AFTER();

    // epilogue -> packed bf16 g_H images
    int lane = tid & 31;
    int sub = w & 3, grp = w >> 2;
    char* Hb = (char*)g_H + (size_t)idx * H_EXP;
    #pragma unroll
    for (int mblk = 0; mblk < 2; ++mblk) {
        int mrow = m0 + mblk * 128 + sub * 32 + lane;
        bool valid = mrow < Nt;
        uint32_t tb = tmem + mblk * 256;
        #pragma unroll
        for (int cc = 0; cc < 4; ++cc) {
            if (dual && cc >= 2) break;
            int coff = dual ? (grp * 32 + cc * 16) : (grp * 64 + cc * 16);
            int fbase = n0 + coff;
            uint32_t d1[16], d2[16];
            TCGEN05_LD_X16(d1, tb + coff);
            if (dual) { TCGEN05_LD_X16(d2, tb + 128 + coff); }
            TCGEN05_WAIT_LD();
            if (valid) {
                #pragma unroll
                for (int v2 = 0; v2 < 2; ++v2) {   // two 16B writes of 8 bf16
                    __nv_bfloat16 o[8];
                    #pragma unroll
                    for (int j = 0; j < 8; ++j) {
                        float h1 = __uint_as_float(d1[v2 * 8 + j]);
                        float r;
                        if (dual) {
                            float h2 = __uint_as_float(d2[v2 * 8 + j]);
                            float sg = 1.f / (1.f + expf(-h2));
                            r = h2 * sg * h2 * h1;
                        } else if (act == 1) {
                            r = 0.5f * h1 * (1.f + erff(h1 * 0.70710678118654752f));
                        } else {
                            r = fmaxf(h1, 0.f);
                        }
                        o[j] = __float2bfloat16(r);
                    }
                    int f = fbase + v2 * 8;
                    char* dst = Hb + (size_t)(f >> 6) * H_CH + (size_t)(mrow >> 7) * 16384
                        + SWZ128((uint32_t)((mrow & 127) * 128 + ((f & 63) >> 3) * 16));
                    *(float4*)dst = *(float4*)o;
                }
            }
        }
    }
    __syncthreads();
    if (tid == 0) {
        MBARRIER_INVAL(ctrl + 8);
        #pragma unroll
        for (int s2 = 0; s2 < NSTG; ++s2) MBARRIER_INVAL(ctrl + 16 + 8 * s2);
    }
    if (w == 0) { TCGEN05_RELINQUISH(); TCGEN05_DEALLOC(tmem, 512); }
#endif
}

// GEMM2: Z = x + H @ W3^T. BM=256, BN=256. NCH = FF/64 = 32.
__global__ void __launch_bounds__(512, 1)
gemm2_tc_kernel(const float* __restrict__ x)
{
#if TC_OK
    int idx = blockIdx.z;
    int Nt = g_cnt[idx];
    int m0 = blockIdx.y * 256;
    if (m0 >= Nt) return;
    int n0 = blockIdx.x * 256;

    const char* Aimg = (const char*)g_H   + (size_t)idx * H_EXP;
    const char* Bimg = (const char*)g_W3t + (size_t)idx * A_EXP;

    extern __shared__ __align__(1024) char smem[];
    uint32_t sb = smem_u32(smem);
    uint32_t ctrl = sb + NSTG * STGB;

    int tid = threadIdx.x;
    int w = tid >> 5;

    if (w == 0) TCGEN05_ALLOC(ctrl, 512);
    if (tid == 0) {
        MBARRIER_INIT(ctrl + 8, 1);
        #pragma unroll
        for (int s2 = 0; s2 < NSTG; ++s2) MBARRIER_INIT(ctrl + 16 + 8 * s2, 1);
    }
    __syncthreads();
    uint32_t tmem;
    asm volatile("ld.shared.b32 %0, [%1];" : "=r"(tmem) : "r"(ctrl));

    const int NCH = FF / 64;   // 32
    if (tid == 0) {
        auto load_chunk = [&](int st, int ch) {
            uint32_t mb = ctrl + 16 + 8 * st;
            uint32_t base = sb + st * STGB;
            MBARRIER_EXPECT_TX(mb, 65536u);
            bulk_g2s(base, Aimg + (size_t)ch * H_CH + (size_t)(m0 >> 7) * 16384, 32768, mb);
            bulk_g2s(base + 32768, Bimg + (size_t)ch * W3_CH + (size_t)(n0 >> 7) * 16384, 32768, mb);
        };
        load_chunk(0, 0);
        load_chunk(1, 1);
        for (int it = 0; it < NCH; ++it) {
            int st = it % NSTG;
            if (it >= 1) MBAR_WAIT(ctrl + 8, (it - 1) & 1);
            if (it + 2 < NCH) load_chunk((it + 2) % NSTG, it + 2);
            MBAR_WAIT(ctrl + 16 + 8 * st, (it / NSTG) & 1);
            uint32_t base = sb + st * STGB;
            #pragma unroll
            for (int m = 0; m < 2; ++m) {
                uint64_t ad = MAKE_SMEM_DESC(base + m * 16384u);
                #pragma unroll
                for (int half = 0; half < 2; ++half) {
                    uint64_t bd = MAKE_SMEM_DESC(base + 32768u + half * 16384u);
                    #pragma unroll
                    for (int k = 0; k < 4; ++k)
                        umma_bf16(tmem + m * 256 + half * 128, ad + 2 * k, bd + 2 * k,
                                  IDESC_BF16_N128, (uint32_t)(it > 0 || k > 0));
                }
            }
            TCGEN05_COMMIT(ctrl + 8);
        }
        MBAR_WAIT(ctrl + 8, (NCH - 1) & 1);
    }
    __syncthreads();
    TCGEN05_FENCE_AFTER();

    int lane = tid & 31;
    int sub = w & 3, grp = w >> 2;
    float* Zb = g_Z + (size_t)idx * TT * DD;
    #pragma unroll
    for (int mblk = 0; mblk < 2; ++mblk) {
        int mrow = m0 + mblk * 128 + sub * 32 + lane;
        bool valid = mrow < Nt;
        int tok = valid ? g_tok[idx * TT + mrow] : 0;
        uint32_t tb = tmem + mblk * 256;
        #pragma unroll
        for (int cc = 0; cc < 4; ++cc) {
            uint32_t d1[16];
            TCGEN05_LD_X16(d1, tb + grp * 64 + cc * 16);
            TCGEN05_WAIT_LD();
            if (valid) {
                const float4* xr = (const float4*)(x + (size_t)tok * DD + n0 + grp * 64 + cc * 16);
                float4* p = (float4*)(Zb + (size_t)mrow * DD + n0 + grp * 64 + cc * 16);
                #pragma unroll
                for (int v = 0; v < 4; ++v) {
                    float4 xv = xr[v];
                    p[v] = make_float4(__uint_as_float(d1[4*v])   + xv.x,
                                       __uint_as_float(d1[4*v+1]) + xv.y,
                                       __uint_as_float(d1[4*v+2]) + xv.z,
                                       __uint_as_float(d1[4*v+3]) + xv.w);
                }
            }
        }
    }
    __syncthreads();
    if (tid == 0) {
        MBARRIER_INVAL(ctrl + 8);
        #pragma unroll
        for (int s2 = 0; s2 < NSTG; ++s2) MBARRIER_INVAL(ctrl + 16 + 8 * s2);
    }
    if (w == 0) { TCGEN05_RELINQUISH(); TCGEN05_DEALLOC(tmem, 512); }
#endif
}

// fused: expert LN + expert combine + cluster LN + gate sum
__global__ void final_kernel(const float* __restrict__ loutg, const float* __restrict__ loutb,
                             const float* __restrict__ clng, const float* __restrict__ clnb,
                             float* __restrict__ out)
{
    int t = blockIdx.x;
    int tid = threadIdx.x;                    // 256
    __shared__ float rbuf[18];
    float o[4] = {};
    #pragma unroll
    for (int sI = 0; sI < 2; sI++) {
        float vcmb[4] = {};
        #pragma unroll
        for (int q = 0; q < 2; q++) {
            int slot = g_islot[t * 4 + sI * 2 + q];
            int pos  = g_ipos [t * 4 + sI * 2 + q];
            float cf = g_icoef[t * 4 + sI * 2 + q];
            const float* y = g_Z + ((size_t)slot * TT + pos) * DD;
            const float* gp = loutg + (size_t)slot * DD;
            const float* bp = loutb + (size_t)slot * DD;
            float v[4], s = 0.f, s2 = 0.f;
            #pragma unroll
            for (int r = 0; r < 4; r++) {
                int d = tid + 256 * r;
                v[r] = y[d]; s += v[r]; s2 += v[r] * v[r];
            }
            float mu, rs;
            block_meanvar_256(s, s2, rbuf, mu, rs);
            #pragma unroll
            for (int r = 0; r < 4; r++) {
                int d = tid + 256 * r;
                vcmb[r] += cf * ((v[r] - mu) * rs * gp[d] + bp[d]);
            }
        }
        float s = 0.f, s2 = 0.f;
        #pragma unroll
        for (int r = 0; r < 4; r++) { s += vcmb[r]; s2 += vcmb[r] * vcmb[r]; }
        float mu, rs;
        block_meanvar_256(s, s2, rbuf, mu, rs);
        int cc = g_sel[t * 2 + sI];
        float gt = g_gate[t * 2 + sI];
        #pragma unroll
        for (int r = 0; r < 4; r++) {
            int d = tid + 256 * r;
            o[r] += gt * ((vcmb[r] - mu) * rs * clng[cc * DD + d] + clnb[cc * DD + d]);
        }
    }
    #pragma unroll
    for (int r = 0; r < 4; r++)
        out[(size_t)t * DD + tid + 256 * r] = o[r];
}

// ---------------- launcher ----------------
extern "C" void kernel_launch(void* const* d_in, const int* in_sizes, int n_in,
                              void* d_out, int out_size)
{
    const float* x     = (const float*)d_in[0];
    const float* W1    = (const float*)d_in[1];
    const float* W2    = (const float*)d_in[2];
    const float* W3    = (const float*)d_in[3];
    const float* ling  = (const float*)d_in[4];
    const float* linb  = (const float*)d_in[5];
    const float* loutg = (const float*)d_in[6];
    const float* loutb = (const float*)d_in[7];
    const float* clng  = (const float*)d_in[8];
    const float* clnb  = (const float*)d_in[9];
    const float* Wrc   = (const float*)d_in[10];
    const float* brc   = (const float*)d_in[11];
    const float* Wre   = (const float*)d_in[12];
    const float* bre   = (const float*)d_in[13];
    float* out = (float*)d_out;

    __nv_bfloat16* w1t; cudaGetSymbolAddress((void**)&w1t, g_W1t);
    __nv_bfloat16* w2t; cudaGetSymbolAddress((void**)&w2t, g_W2t);
    __nv_bfloat16* w3t; cudaGetSymbolAddress((void**)&w3t, g_W3t);

    cudaFuncSetAttribute(gemm1_tc_kernel,
                         cudaFuncAttributeMaxDynamicSharedMemorySize, SMEM_TC);
    cudaFuncSetAttribute(gemm2_tc_kernel,
                         cudaFuncAttributeMaxDynamicSharedMemorySize, SMEM_TC);
    cudaFuncSetAttribute(routing_kernel,
                         cudaFuncAttributeMaxDynamicSharedMemorySize, RT_SMEM);

    // fork-join: packs on side stream, concurrent with routing/prep
    cudaStream_t sB;
    cudaStreamCreateWithFlags(&sB, cudaStreamNonBlocking);
    cudaEvent_t eFork, eJoin12, eJoin3;
    cudaEventCreateWithFlags(&eFork,   cudaEventDisableTiming);
    cudaEventCreateWithFlags(&eJoin12, cudaEventDisableTiming);
    cudaEventCreateWithFlags(&eJoin3,  cudaEventDisableTiming);

    zero_cnt_kernel<<<1, 32>>>();
    cudaEventRecord(eFork, 0);
    cudaStreamWaitEvent(sB, eFork, 0);

    // branch B: weight packs (64k x 128n tiles)
    pack_kernel<<<dim3(FF/128, DD/64, 16), 256, 0, sB>>>(W1, w1t, DD, FF, 0);
    pack_kernel<<<dim3(FF/128, DD/64, 8),  256, 0, sB>>>(W2, w2t, DD, FF, 1);
    cudaEventRecord(eJoin12, sB);
    pack_kernel<<<dim3(DD/128, FF/64, 16), 256, 0, sB>>>(W3, w3t, FF, DD, 0);
    cudaEventRecord(eJoin3, sB);

    // main branch
    routing_kernel<<<TT/32, 1024, RT_SMEM>>>(x, Wrc, brc, Wre, bre);
    dim3 gp(TT, NEXP);
    prep_kernel<<<gp, 128>>>(x, ling, linb);

    cudaStreamWaitEvent(0, eJoin12, 0);
    dim3 g1(FF/128, 4, NEXP);
    gemm1_tc_kernel<<<g1, 512, SMEM_TC>>>();

    cudaStreamWaitEvent(0, eJoin3, 0);
    dim3 g2(DD/256, 4, NEXP);
    gemm2_tc_kernel<<<g2, 512, SMEM_TC>>>(x);

    final_kernel<<<TT, 256>>>(loutg, loutb, clng, clnb, out);
}